// round 2
// baseline (speedup 1.0000x reference)
#include <cuda_runtime.h>
#include <math.h>

#define BATCH   16
#define HEADS   16
#define DIM     128
#define BS      16
#define MAX_CTX 1024
#define NTBL    96
#define PT_LEN  32
#define QSCALE  0.08838834764831845f
#define CHUNK   256
#define NCHUNK  4
#define NEG_INF -1e30f

// split-context partials + fan-in counters (allocation-free: __device__ globals)
__device__ float        g_m  [BATCH*HEADS*NCHUNK];
__device__ float        g_l  [BATCH*HEADS*NCHUNK];
__device__ float        g_acc[BATCH*HEADS*NCHUNK*DIM];
__device__ unsigned int g_cnt[BATCH*HEADS];          // zero-init; merger resets

__global__ void __launch_bounds__(128) attn_fused(
    const float* __restrict__ q,
    const float* __restrict__ k_new,
    const float* __restrict__ v_new,
    const float* __restrict__ kc,
    const float* __restrict__ vc,
    const int*   __restrict__ btab,
    const int*   __restrict__ ctx_lens,
    const float* __restrict__ bias,
    float*       __restrict__ out)
{
    const int chunk = blockIdx.x;
    const int h     = blockIdx.y;
    const int b     = blockIdx.z;
    const int ctx   = ctx_lens[b];
    const int start = chunk * CHUNK;
    if (start >= ctx) return;

    const int t    = threadIdx.x;          // 0..127
    const int wid  = t >> 5;
    const int lane = t & 31;
    const int bh   = b*HEADS + h;
    const int npos = min(CHUNK, ctx - start);
    const int nblk = (npos + BS - 1) / BS;
    const int last = ctx - 1;

    __shared__ float sh_s[CHUNK];          // scores -> probs
    __shared__ int   sh_blk[CHUNK/BS];     // 16 block ids
    __shared__ float sh_red[9];            // [0..3] max partials, [4..7] sum partials, [8] flag

    if (t < nblk) sh_blk[t] = btab[b*NTBL + PT_LEN + chunk*(CHUNK/BS) + t];

    // q float4 per lane (dims 4*lane..4*lane+3), pre-scaled
    float4 q4 = ((const float4*)(q + (size_t)bh*DIM))[lane];
    q4.x *= QSCALE; q4.y *= QSCALE; q4.z *= QSCALE; q4.w *= QSCALE;
    __syncthreads();

    // ---------- Phase A: all scores (independent chains -> deep MLP) ----------
    #pragma unroll 4
    for (int p = wid; p < CHUNK; p += 4) {        // p uniform across the warp
        float sval = NEG_INF;
        if (p < npos) {
            const int pos = start + p;
            const float* kptr = (pos == last)
                ? (k_new + (size_t)bh*DIM)
                : (kc + ((size_t)sh_blk[p >> 4]*HEADS + h)*(BS*DIM) + (p & 15)*DIM);
            const float4 k4 = ((const float4*)kptr)[lane];
            float s = q4.x*k4.x + q4.y*k4.y + q4.z*k4.z + q4.w*k4.w;
            #pragma unroll
            for (int o = 16; o > 0; o >>= 1) s += __shfl_xor_sync(0xffffffffu, s, o);
            sval = s + bias[(size_t)bh*MAX_CTX + pos];
        }
        if (lane == 0) sh_s[p] = sval;
    }
    __syncthreads();

    // ---------- Phase B: softmax over the chunk ----------
    const float s0 = sh_s[t], s1 = sh_s[t + 128];
    float mx = fmaxf(s0, s1);
    #pragma unroll
    for (int o = 16; o > 0; o >>= 1) mx = fmaxf(mx, __shfl_xor_sync(0xffffffffu, mx, o));
    if (lane == 0) sh_red[wid] = mx;
    __syncthreads();
    const float M = fmaxf(fmaxf(sh_red[0], sh_red[1]), fmaxf(sh_red[2], sh_red[3]));
    const float p0 = __expf(s0 - M), p1 = __expf(s1 - M);
    float sum = p0 + p1;
    #pragma unroll
    for (int o = 16; o > 0; o >>= 1) sum += __shfl_xor_sync(0xffffffffu, sum, o);
    if (lane == 0) sh_red[4 + wid] = sum;
    sh_s[t] = p0; sh_s[t + 128] = p1;
    __syncthreads();
    const float L = sh_red[4] + sh_red[5] + sh_red[6] + sh_red[7];

    // ---------- Phase C: V accumulate (thread t owns dim t; blocks independent) ----------
    float acc = 0.f;
    #pragma unroll 4
    for (int kb = 0; kb < CHUNK/BS; ++kb) {
        if (kb >= nblk) break;
        const float4* vp = (const float4*)(vc + ((size_t)sh_blk[kb]*HEADS + h)*(DIM*BS) + t*BS);
        const float4 v0 = vp[0], v1 = vp[1], v2 = vp[2], v3 = vp[3];
        float vv[BS] = {v0.x,v0.y,v0.z,v0.w, v1.x,v1.y,v1.z,v1.w,
                        v2.x,v2.y,v2.z,v2.w, v3.x,v3.y,v3.z,v3.w};
        const int pbase = start + kb*BS;
        if (last >= pbase && last < pbase + BS)
            vv[last - pbase] = v_new[(size_t)bh*DIM + t];
        float a = 0.f;
        #pragma unroll
        for (int j = 0; j < BS; ++j) a += sh_s[kb*BS + j] * vv[j];
        acc += a;
    }

    const int nch = (ctx + CHUNK - 1) / CHUNK;
    if (nch == 1) {                         // sole chunk: write output directly
        out[(size_t)bh*DIM + t] = acc / L;
        return;
    }

    // ---------- write partial + fan-in merge (last CTA for this (b,h)) ----------
    const int base = bh*NCHUNK;
    const int idx  = base + chunk;
    if (t == 0) { g_m[idx] = M; g_l[idx] = L; }
    g_acc[(size_t)idx*DIM + t] = acc;
    __threadfence();
    __syncthreads();
    if (t == 0) {
        const unsigned int ticket = atomicAdd(&g_cnt[bh], 1u);
        sh_red[8] = (ticket == (unsigned)(nch - 1)) ? 1.f : 0.f;
    }
    __syncthreads();
    if (sh_red[8] != 0.f) {
        float mc[NCHUNK], lc[NCHUNK];
        #pragma unroll
        for (int c = 0; c < NCHUNK; ++c) {
            mc[c] = (c < nch) ? g_m[base + c] : NEG_INF;
            lc[c] = (c < nch) ? g_l[base + c] : 0.f;
        }
        float MM = NEG_INF;
        #pragma unroll
        for (int c = 0; c < NCHUNK; ++c) MM = fmaxf(MM, mc[c]);
        float LL = 0.f, o = 0.f;
        float w[NCHUNK];
        #pragma unroll
        for (int c = 0; c < NCHUNK; ++c) { w[c] = __expf(mc[c] - MM); LL += lc[c] * w[c]; }
        #pragma unroll
        for (int c = 0; c < NCHUNK; ++c)
            if (c < nch) o += w[c] * g_acc[(size_t)(base + c)*DIM + t];
        out[(size_t)bh*DIM + t] = o / LL;
        if (t == 0) g_cnt[bh] = 0u;         // reset for next graph replay
    }
}

extern "C" void kernel_launch(void* const* d_in, const int* in_sizes, int n_in,
                              void* d_out, int out_size)
{
    const float* q     = (const float*)d_in[0];
    const float* k_new = (const float*)d_in[1];
    const float* v_new = (const float*)d_in[2];
    const float* kc    = (const float*)d_in[3];
    const float* vc    = (const float*)d_in[4];
    const int*   btab  = (const int*)d_in[6];
    const int*   ctx   = (const int*)d_in[7];
    const float* bias  = (const float*)d_in[8];

    dim3 g(NCHUNK, HEADS, BATCH);
    attn_fused<<<g, 128>>>(q, k_new, v_new, kc, vc, btab, ctx, bias, (float*)d_out);
}

// round 3
// speedup vs baseline: 1.1918x; 1.1918x over previous
#include <cuda_runtime.h>
#include <math.h>

#define BATCH   16
#define HEADS   16
#define DIM     128
#define BS      16
#define MAX_CTX 1024
#define NTBL    96
#define PT_LEN  32
#define QSCALE  0.08838834764831845f
#define CHUNK   64
#define NCHUNK  16
#define NEG_INF -1e30f

// split-context partials + fan-in counters (allocation-free: __device__ globals)
__device__ float        g_m  [BATCH*HEADS*NCHUNK];
__device__ float        g_l  [BATCH*HEADS*NCHUNK];
__device__ float        g_acc[BATCH*HEADS*NCHUNK*DIM];
__device__ unsigned int g_cnt[BATCH*HEADS];          // zero-init; merger resets

__global__ void __launch_bounds__(128) attn_fused(
    const float* __restrict__ q,
    const float* __restrict__ k_new,
    const float* __restrict__ v_new,
    const float* __restrict__ kc,
    const float* __restrict__ vc,
    const int*   __restrict__ btab,
    const int*   __restrict__ ctx_lens,
    const float* __restrict__ bias,
    float*       __restrict__ out)
{
    const int chunk = blockIdx.x;
    const int h     = blockIdx.y;
    const int b     = blockIdx.z;
    const int ctx   = ctx_lens[b];
    const int start = chunk * CHUNK;
    if (start >= ctx) return;

    const int t    = threadIdx.x;          // 0..127
    const int wid  = t >> 5;
    const int lane = t & 31;
    const int bh   = b*HEADS + h;
    const int npos = min(CHUNK, ctx - start);
    const int last = ctx - 1;

    __shared__ float sh_s[CHUNK];          // scores -> probs
    __shared__ int   sh_blk[CHUNK/BS];     // 4 block ids
    __shared__ float sh_red[5];            // [0,1] warp maxes, [2,3] warp sums, [4] flag

    if (t < CHUNK/BS) sh_blk[t] = btab[b*NTBL + PT_LEN + chunk*(CHUNK/BS) + t];

    // q float4 per lane (dims 4*lane..4*lane+3), pre-scaled
    float4 q4 = ((const float4*)(q + (size_t)bh*DIM))[lane];
    q4.x *= QSCALE; q4.y *= QSCALE; q4.z *= QSCALE; q4.w *= QSCALE;
    __syncthreads();

    // ---------- Phase A: warp `wid` owns cache block `wid` (16 contiguous rows) ----------
    {
        const float* kbase = kc + ((size_t)sh_blk[wid]*HEADS + h)*(BS*DIM);
        #pragma unroll 8
        for (int i = 0; i < BS; ++i) {
            const int p = wid*BS + i;
            float sval = NEG_INF;
            if (p < npos) {
                const int pos = start + p;
                const float* kptr = (pos == last) ? (k_new + (size_t)bh*DIM)
                                                  : (kbase + i*DIM);
                const float4 k4 = ((const float4*)kptr)[lane];
                float s = q4.x*k4.x + q4.y*k4.y + q4.z*k4.z + q4.w*k4.w;
                #pragma unroll
                for (int o = 16; o > 0; o >>= 1) s += __shfl_xor_sync(0xffffffffu, s, o);
                sval = s + bias[(size_t)bh*MAX_CTX + pos];
            }
            if (lane == 0) sh_s[p] = sval;
        }
    }
    __syncthreads();

    // ---------- Phase B: softmax over 64 scores (warps 0,1 active) ----------
    const float sc = (t < CHUNK) ? sh_s[t] : NEG_INF;
    float mx = sc;
    #pragma unroll
    for (int o = 16; o > 0; o >>= 1) mx = fmaxf(mx, __shfl_xor_sync(0xffffffffu, mx, o));
    if (t < CHUNK && lane == 0) sh_red[wid] = mx;
    __syncthreads();
    const float M  = fmaxf(sh_red[0], sh_red[1]);
    const float pv = (t < CHUNK) ? __expf(sc - M) : 0.f;
    float sum = pv;
    #pragma unroll
    for (int o = 16; o > 0; o >>= 1) sum += __shfl_xor_sync(0xffffffffu, sum, o);
    if (t < CHUNK && lane == 0) sh_red[2 + wid] = sum;
    if (t < CHUNK) sh_s[t] = pv;
    __syncthreads();
    const float L = sh_red[2] + sh_red[3];

    // ---------- Phase C: V accumulate (thread t owns dim t; 4 independent blocks) ----------
    float acc = 0.f;
    #pragma unroll
    for (int kb = 0; kb < CHUNK/BS; ++kb) {
        if (kb*BS >= npos) break;
        const float4* vp = (const float4*)(vc + ((size_t)sh_blk[kb]*HEADS + h)*(DIM*BS) + t*BS);
        const float4 v0 = vp[0], v1 = vp[1], v2 = vp[2], v3 = vp[3];
        float vv[BS] = {v0.x,v0.y,v0.z,v0.w, v1.x,v1.y,v1.z,v1.w,
                        v2.x,v2.y,v2.z,v2.w, v3.x,v3.y,v3.z,v3.w};
        const int pbase = start + kb*BS;
        if (last >= pbase && last < pbase + BS)
            vv[last - pbase] = v_new[(size_t)bh*DIM + t];
        float a = 0.f;
        #pragma unroll
        for (int j = 0; j < BS; ++j) a += sh_s[kb*BS + j] * vv[j];
        acc += a;
    }

    const int nch = (ctx + CHUNK - 1) / CHUNK;
    if (nch == 1) {                         // sole chunk: write output directly
        out[(size_t)bh*DIM + t] = acc / L;
        return;
    }

    // ---------- write partial + fan-in merge (last CTA for this (b,h)) ----------
    const int base = bh*NCHUNK;
    const int idx  = base + chunk;
    if (t == 0) { g_m[idx] = M; g_l[idx] = L; }
    g_acc[(size_t)idx*DIM + t] = acc;
    __threadfence();
    __syncthreads();
    if (t == 0) {
        const unsigned int ticket = atomicAdd(&g_cnt[bh], 1u);
        sh_red[4] = (ticket == (unsigned)(nch - 1)) ? 1.f : 0.f;
    }
    __syncthreads();
    if (sh_red[4] != 0.f) {
        float MM = NEG_INF;
        for (int c = 0; c < nch; ++c) MM = fmaxf(MM, g_m[base + c]);
        float LL = 0.f, o = 0.f;
        for (int c = 0; c < nch; ++c) {
            const float w = __expf(g_m[base + c] - MM);
            LL += g_l[base + c] * w;
            o  += w * g_acc[(size_t)(base + c)*DIM + t];
        }
        out[(size_t)bh*DIM + t] = o / LL;
        if (t == 0) g_cnt[bh] = 0u;         // reset for next graph replay
    }
}

extern "C" void kernel_launch(void* const* d_in, const int* in_sizes, int n_in,
                              void* d_out, int out_size)
{
    const float* q     = (const float*)d_in[0];
    const float* k_new = (const float*)d_in[1];
    const float* v_new = (const float*)d_in[2];
    const float* kc    = (const float*)d_in[3];
    const float* vc    = (const float*)d_in[4];
    const int*   btab  = (const int*)d_in[6];
    const int*   ctx   = (const int*)d_in[7];
    const float* bias  = (const float*)d_in[8];

    dim3 g(NCHUNK, HEADS, BATCH);
    attn_fused<<<g, 128>>>(q, k_new, v_new, kc, vc, btab, ctx, bias, (float*)d_out);
}

// round 4
// speedup vs baseline: 1.4993x; 1.2581x over previous
#include <cuda_runtime.h>
#include <math.h>

#define BATCH   16
#define HEADS   16
#define DIM     128
#define BS      16
#define MAX_CTX 1024
#define NTBL    96
#define PT_LEN  32
#define QSCALE  0.08838834764831845f
#define CHUNK   64
#define NCHUNK  16
#define NEG_INF -1e30f

__device__ float        g_m  [BATCH*HEADS*NCHUNK];
__device__ float        g_l  [BATCH*HEADS*NCHUNK];
__device__ float        g_acc[BATCH*HEADS*NCHUNK*DIM];
__device__ unsigned int g_cnt[BATCH*HEADS];          // zero-init; merger resets

__global__ void __launch_bounds__(128, 6) attn_fused(
    const float* __restrict__ q,
    const float* __restrict__ k_new,
    const float* __restrict__ v_new,
    const float* __restrict__ kc,
    const float* __restrict__ vc,
    const int*   __restrict__ btab,
    const int*   __restrict__ ctx_lens,
    const float* __restrict__ bias,
    float*       __restrict__ out)
{
    const int chunk = blockIdx.x;
    const int h     = blockIdx.y;
    const int b     = blockIdx.z;
    const int ctx   = ctx_lens[b];
    const int start = chunk * CHUNK;
    if (start >= ctx) return;

    const int t    = threadIdx.x;          // 0..127
    const int wid  = t >> 5;
    const int lane = t & 31;
    const int bh   = b*HEADS + h;
    const int npos = min(CHUNK, ctx - start);
    const int last = ctx - 1;

    __shared__ float sh_s[CHUNK];
    __shared__ int   sh_blk[CHUNK/BS];
    __shared__ float sh_red[5];

    if (t < CHUNK/BS) sh_blk[t] = btab[b*NTBL + PT_LEN + chunk*(CHUNK/BS) + t];

    float4 q4 = ((const float4*)(q + (size_t)bh*DIM))[lane];
    q4.x *= QSCALE; q4.y *= QSCALE; q4.z *= QSCALE; q4.w *= QSCALE;
    const float vn = v_new[(size_t)bh*DIM + t];         // substitution value for dim t
    __syncthreads();

    // ---------- Phase A: warp owns cache block `wid`; 8-deep batched loads ----------
    if (wid*BS < npos) {
        const float* kbase  = kc + ((size_t)sh_blk[wid]*HEADS + h)*(BS*DIM);
        const float* knewp  = k_new + (size_t)bh*DIM;
        #pragma unroll
        for (int half = 0; half < 2; ++half) {
            float4 kr[8];
            #pragma unroll
            for (int i = 0; i < 8; ++i) {
                const int row = half*8 + i;
                const int pos = start + wid*BS + row;
                const float* kp = (pos == last) ? knewp : (kbase + row*DIM);
                kr[i] = ((const float4*)kp)[lane];
            }
            float sp[8];
            #pragma unroll
            for (int i = 0; i < 8; ++i)
                sp[i] = q4.x*kr[i].x + q4.y*kr[i].y + q4.z*kr[i].z + q4.w*kr[i].w;
            #pragma unroll
            for (int o = 16; o > 0; o >>= 1)
                #pragma unroll
                for (int i = 0; i < 8; ++i)
                    sp[i] += __shfl_xor_sync(0xffffffffu, sp[i], o);
            if (lane == 0) {
                #pragma unroll
                for (int i = 0; i < 8; ++i) {
                    const int p   = wid*BS + half*8 + i;
                    const int pos = start + p;
                    sh_s[p] = (pos < ctx) ? sp[i] + bias[(size_t)bh*MAX_CTX + pos]
                                          : NEG_INF;
                }
            }
        }
    } else if (lane < BS) {
        sh_s[wid*BS + lane] = NEG_INF;
    }
    __syncthreads();

    // ---------- Phase B: softmax over 64 scores ----------
    const float sc = (t < CHUNK) ? sh_s[t] : NEG_INF;
    float mx = sc;
    #pragma unroll
    for (int o = 16; o > 0; o >>= 1) mx = fmaxf(mx, __shfl_xor_sync(0xffffffffu, mx, o));
    if (t < CHUNK && lane == 0) sh_red[wid] = mx;
    __syncthreads();
    const float M  = fmaxf(sh_red[0], sh_red[1]);
    const float pv = (t < CHUNK) ? __expf(sc - M) : 0.f;
    float sum = pv;
    #pragma unroll
    for (int o = 16; o > 0; o >>= 1) sum += __shfl_xor_sync(0xffffffffu, sum, o);
    if (t < CHUNK && lane == 0) sh_red[2 + wid] = sum;
    if (t < CHUNK) sh_s[t] = pv;
    __syncthreads();
    const float L = sh_red[2] + sh_red[3];

    // ---------- Phase C: V accumulate, 2 blocks batched per half ----------
    float acc = 0.f;
    #pragma unroll
    for (int half = 0; half < 2; ++half) {
        if (half*2*BS >= npos) break;
        const int kb0 = half*2, kb1 = half*2 + 1;
        const float4* vp0 = (const float4*)(vc + ((size_t)sh_blk[kb0]*HEADS + h)*(DIM*BS) + t*BS);
        const float4* vp1 = (const float4*)(vc + ((size_t)sh_blk[kb1]*HEADS + h)*(DIM*BS) + t*BS);
        float4 a0 = vp0[0], a1 = vp0[1], a2 = vp0[2], a3 = vp0[3];
        float4 b0 = vp1[0], b1 = vp1[1], b2 = vp1[2], b3 = vp1[3];
        float va[16] = {a0.x,a0.y,a0.z,a0.w, a1.x,a1.y,a1.z,a1.w,
                        a2.x,a2.y,a2.z,a2.w, a3.x,a3.y,a3.z,a3.w};
        float vb[16] = {b0.x,b0.y,b0.z,b0.w, b1.x,b1.y,b1.z,b1.w,
                        b2.x,b2.y,b2.z,b2.w, b3.x,b3.y,b3.z,b3.w};
        const int li0 = last - (start + kb0*BS);
        const int li1 = last - (start + kb1*BS);
        #pragma unroll
        for (int j = 0; j < BS; ++j) {
            if (j == li0) va[j] = vn;       // constant-index compare -> SEL
            if (j == li1) vb[j] = vn;
            acc += sh_s[kb0*BS + j] * va[j];
            acc += sh_s[kb1*BS + j] * vb[j];
        }
    }

    const int nch = (ctx + CHUNK - 1) / CHUNK;
    if (nch == 1) {
        out[(size_t)bh*DIM + t] = acc / L;
        return;
    }

    // ---------- partial write + fan-in merge ----------
    const int base = bh*NCHUNK;
    const int idx  = base + chunk;
    if (t == 0) { g_m[idx] = M; g_l[idx] = L; }
    g_acc[(size_t)idx*DIM + t] = acc;
    __threadfence();
    __syncthreads();
    if (t == 0) {
        const unsigned int ticket = atomicAdd(&g_cnt[bh], 1u);
        sh_red[4] = (ticket == (unsigned)(nch - 1)) ? 1.f : 0.f;
    }
    __syncthreads();
    if (sh_red[4] != 0.f) {
        float MM = NEG_INF;
        for (int c = 0; c < nch; ++c) MM = fmaxf(MM, g_m[base + c]);
        float LL = 0.f, o = 0.f;
        for (int c = 0; c < nch; ++c) {
            const float w = __expf(g_m[base + c] - MM);
            LL += g_l[base + c] * w;
            o  += w * g_acc[(size_t)(base + c)*DIM + t];
        }
        out[(size_t)bh*DIM + t] = o / LL;
        if (t == 0) g_cnt[bh] = 0u;
    }
}

extern "C" void kernel_launch(void* const* d_in, const int* in_sizes, int n_in,
                              void* d_out, int out_size)
{
    const float* q     = (const float*)d_in[0];
    const float* k_new = (const float*)d_in[1];
    const float* v_new = (const float*)d_in[2];
    const float* kc    = (const float*)d_in[3];
    const float* vc    = (const float*)d_in[4];
    const int*   btab  = (const int*)d_in[6];
    const int*   ctx   = (const int*)d_in[7];
    const float* bias  = (const float*)d_in[8];

    dim3 g(NCHUNK, HEADS, BATCH);
    attn_fused<<<g, 128>>>(q, k_new, v_new, kc, vc, btab, ctx, bias, (float*)d_out);
}

// round 5
// speedup vs baseline: 1.6308x; 1.0877x over previous
#include <cuda_runtime.h>
#include <math.h>

#define BATCH   16
#define HEADS   16
#define DIM     128
#define BS      16
#define MAX_CTX 1024
#define NTBL    96
#define PT_LEN  32
#define QSCALE  0.08838834764831845f
#define CHUNK   64
#define NCHUNK  16
#define NEG_INF -1e30f

__device__ float        g_m  [BATCH*HEADS*NCHUNK];
__device__ float        g_l  [BATCH*HEADS*NCHUNK];
__device__ float        g_acc[BATCH*HEADS*NCHUNK*DIM];
__device__ unsigned int g_cnt[BATCH*HEADS];          // zero-init; merger resets

__global__ void __launch_bounds__(128, 6) attn_fused(
    const float* __restrict__ q,
    const float* __restrict__ k_new,
    const float* __restrict__ v_new,
    const float* __restrict__ kc,
    const float* __restrict__ vc,
    const int*   __restrict__ btab,
    const int*   __restrict__ ctx_lens,
    const float* __restrict__ bias,
    float*       __restrict__ out)
{
    const int chunk = blockIdx.x;
    const int h     = blockIdx.y;
    const int b     = blockIdx.z;
    const int ctx   = ctx_lens[b];
    const int start = chunk * CHUNK;
    if (start >= ctx) return;

    const int t    = threadIdx.x;          // 0..127
    const int wid  = t >> 5;
    const int lane = t & 31;
    const int bh   = b*HEADS + h;
    const int npos = min(CHUNK, ctx - start);
    const int last = ctx - 1;

    __shared__ float shK[CHUNK*DIM];       // 32 KB K staging
    __shared__ float sh_s[CHUNK];          // scores -> probs
    __shared__ float sh_b[CHUNK];          // bias
    __shared__ int   sh_blk[CHUNK/BS];
    __shared__ float sh_red[5];

    if (t < CHUNK/BS) sh_blk[t] = btab[b*NTBL + PT_LEN + chunk*(CHUNK/BS) + t];
    if (t < CHUNK)    sh_b[t]   = bias[(size_t)bh*MAX_CTX + start + t];   // start+t < 1024 always

    float4 q4 = ((const float4*)(q + (size_t)bh*DIM))[lane];
    q4.x *= QSCALE; q4.y *= QSCALE; q4.z *= QSCALE; q4.w *= QSCALE;
    const float vn = v_new[(size_t)bh*DIM + t];
    __syncthreads();

    // ---------- Phase A: warp `wid` streams its 16-row block via cp.async (depth 16) ----------
    {
        const float* kbase = kc + ((size_t)sh_blk[wid]*HEADS + h)*(BS*DIM);
        const float* knewp = k_new + (size_t)bh*DIM;
        const unsigned dbase = (unsigned)__cvta_generic_to_shared(&shK[wid*BS*DIM]) + lane*16u;
        #pragma unroll
        for (int r = 0; r < BS; ++r) {
            const int pos = start + wid*BS + r;
            const float* src = ((pos == last) ? knewp : (kbase + r*DIM)) + lane*4;
            asm volatile("cp.async.cg.shared.global [%0], [%1], 16;\n"
                         :: "r"(dbase + r*(DIM*4u)), "l"(src) : "memory");
        }
        asm volatile("cp.async.commit_group;\n" ::: "memory");
        asm volatile("cp.async.wait_group 0;\n"  ::: "memory");
        __syncwarp();

        // dots from shared (warp reads contiguous 512B rows: conflict-free)
        #pragma unroll
        for (int half = 0; half < 2; ++half) {
            float sp[8];
            #pragma unroll
            for (int i = 0; i < 8; ++i) {
                const float4 k4 = *(const float4*)&shK[(wid*BS + half*8 + i)*DIM + lane*4];
                sp[i] = q4.x*k4.x + q4.y*k4.y + q4.z*k4.z + q4.w*k4.w;
            }
            #pragma unroll
            for (int o = 16; o > 0; o >>= 1)
                #pragma unroll
                for (int i = 0; i < 8; ++i)
                    sp[i] += __shfl_xor_sync(0xffffffffu, sp[i], o);
            if (lane == 0) {
                #pragma unroll
                for (int i = 0; i < 8; ++i)
                    sh_s[wid*BS + half*8 + i] = sp[i];
            }
        }
    }
    __syncthreads();

    // ---------- V half-0 loads issued BEFORE softmax (latency hidden under Phase B) ----------
    const float4* vp0 = (const float4*)(vc + ((size_t)sh_blk[0]*HEADS + h)*(DIM*BS) + t*BS);
    const float4* vp1 = (const float4*)(vc + ((size_t)sh_blk[1]*HEADS + h)*(DIM*BS) + t*BS);
    float4 a0 = vp0[0], a1 = vp0[1], a2 = vp0[2], a3 = vp0[3];
    float4 b0 = vp1[0], b1 = vp1[1], b2 = vp1[2], b3 = vp1[3];

    // ---------- Phase B: softmax over 64 scores (+bias, +mask) ----------
    const float sc = (t < npos) ? sh_s[t] + sh_b[t] : NEG_INF;
    float mx = sc;
    #pragma unroll
    for (int o = 16; o > 0; o >>= 1) mx = fmaxf(mx, __shfl_xor_sync(0xffffffffu, mx, o));
    if (t < CHUNK && lane == 0) sh_red[wid] = mx;
    __syncthreads();
    const float M  = fmaxf(sh_red[0], sh_red[1]);
    const float pv = (t < CHUNK) ? __expf(sc - M) : 0.f;   // masked -> exactly 0
    float sum = pv;
    #pragma unroll
    for (int o = 16; o > 0; o >>= 1) sum += __shfl_xor_sync(0xffffffffu, sum, o);
    if (t < CHUNK && lane == 0) sh_red[2 + wid] = sum;
    if (t < CHUNK) sh_s[t] = pv;
    __syncthreads();
    const float L = sh_red[2] + sh_red[3];

    // ---------- Phase C: V accumulate (zero probs kill invalid positions; no guards) ----------
    float acc = 0.f;
    {
        float va[16] = {a0.x,a0.y,a0.z,a0.w, a1.x,a1.y,a1.z,a1.w,
                        a2.x,a2.y,a2.z,a2.w, a3.x,a3.y,a3.z,a3.w};
        float vb[16] = {b0.x,b0.y,b0.z,b0.w, b1.x,b1.y,b1.z,b1.w,
                        b2.x,b2.y,b2.z,b2.w, b3.x,b3.y,b3.z,b3.w};
        const int li0 = last - start;
        const int li1 = last - (start + BS);
        #pragma unroll
        for (int j = 0; j < BS; ++j) {
            if (j == li0) va[j] = vn;
            if (j == li1) vb[j] = vn;
            acc += sh_s[j]      * va[j];
            acc += sh_s[BS + j] * vb[j];
        }
    }
    {
        const float4* vp2 = (const float4*)(vc + ((size_t)sh_blk[2]*HEADS + h)*(DIM*BS) + t*BS);
        const float4* vp3 = (const float4*)(vc + ((size_t)sh_blk[3]*HEADS + h)*(DIM*BS) + t*BS);
        float4 c0 = vp2[0], c1 = vp2[1], c2 = vp2[2], c3 = vp2[3];
        float4 d0 = vp3[0], d1 = vp3[1], d2 = vp3[2], d3 = vp3[3];
        float vcc[16] = {c0.x,c0.y,c0.z,c0.w, c1.x,c1.y,c1.z,c1.w,
                         c2.x,c2.y,c2.z,c2.w, c3.x,c3.y,c3.z,c3.w};
        float vd[16] = {d0.x,d0.y,d0.z,d0.w, d1.x,d1.y,d1.z,d1.w,
                        d2.x,d2.y,d2.z,d2.w, d3.x,d3.y,d3.z,d3.w};
        const int li2 = last - (start + 2*BS);
        const int li3 = last - (start + 3*BS);
        #pragma unroll
        for (int j = 0; j < BS; ++j) {
            if (j == li2) vcc[j] = vn;
            if (j == li3) vd[j]  = vn;
            acc += sh_s[2*BS + j] * vcc[j];
            acc += sh_s[3*BS + j] * vd[j];
        }
    }

    const int nch = (ctx + CHUNK - 1) / CHUNK;
    if (nch == 1) {
        out[(size_t)bh*DIM + t] = acc / L;
        return;
    }

    // ---------- partial write + fan-in merge ----------
    const int base = bh*NCHUNK;
    const int idx  = base + chunk;
    if (t == 0) { g_m[idx] = M; g_l[idx] = L; }
    g_acc[(size_t)idx*DIM + t] = acc;
    __threadfence();
    __syncthreads();
    if (t == 0) {
        const unsigned int ticket = atomicAdd(&g_cnt[bh], 1u);
        sh_red[4] = (ticket == (unsigned)(nch - 1)) ? 1.f : 0.f;
    }
    __syncthreads();
    if (sh_red[4] != 0.f) {
        float MM = NEG_INF;
        for (int c = 0; c < nch; ++c) MM = fmaxf(MM, g_m[base + c]);
        float LL = 0.f, o = 0.f;
        for (int c = 0; c < nch; ++c) {
            const float w = __expf(g_m[base + c] - MM);
            LL += g_l[base + c] * w;
            o  += w * g_acc[(size_t)(base + c)*DIM + t];
        }
        out[(size_t)bh*DIM + t] = o / LL;
        if (t == 0) g_cnt[bh] = 0u;
    }
}

extern "C" void kernel_launch(void* const* d_in, const int* in_sizes, int n_in,
                              void* d_out, int out_size)
{
    const float* q     = (const float*)d_in[0];
    const float* k_new = (const float*)d_in[1];
    const float* v_new = (const float*)d_in[2];
    const float* kc    = (const float*)d_in[3];
    const float* vc    = (const float*)d_in[4];
    const int*   btab  = (const int*)d_in[6];
    const int*   ctx   = (const int*)d_in[7];
    const float* bias  = (const float*)d_in[8];

    dim3 g(NCHUNK, HEADS, BATCH);
    attn_fused<<<g, 128>>>(q, k_new, v_new, kc, vc, btab, ctx, bias, (float*)d_out);
}

// round 6
// speedup vs baseline: 1.7402x; 1.0671x over previous
#include <cuda_runtime.h>
#include <math.h>

#define BATCH   16
#define HEADS   16
#define DIM     128
#define BS      16
#define MAX_CTX 1024
#define NTBL    96
#define PT_LEN  32
#define QSCALE  0.08838834764831845f
#define CHUNK   32
#define NCHUNK  32
#define NEG_INF -1e30f

__device__ float        g_m  [BATCH*HEADS*NCHUNK];
__device__ float        g_l  [BATCH*HEADS*NCHUNK];
__device__ float        g_acc[BATCH*HEADS*NCHUNK*DIM];
__device__ unsigned int g_cnt[BATCH*HEADS];          // zero-init; merger resets

__global__ void __launch_bounds__(128, 8) attn_fused(
    const float* __restrict__ q,
    const float* __restrict__ k_new,
    const float* __restrict__ v_new,
    const float* __restrict__ kc,
    const float* __restrict__ vc,
    const int*   __restrict__ btab,
    const int*   __restrict__ ctx_lens,
    const float* __restrict__ bias,
    float*       __restrict__ out)
{
    const int chunk = blockIdx.x;
    const int h     = blockIdx.y;
    const int b     = blockIdx.z;
    const int ctx   = ctx_lens[b];
    const int start = chunk * CHUNK;
    if (start >= ctx) return;

    const int t    = threadIdx.x;          // 0..127
    const int wid  = t >> 5;
    const int lane = t & 31;
    const int bh   = b*HEADS + h;
    const int npos = min(CHUNK, ctx - start);
    const int last = ctx - 1;

    __shared__ float shK[CHUNK*DIM];       // 16 KB K staging
    __shared__ float sh_s[CHUNK];          // scores -> probs
    __shared__ float sh_b[CHUNK];          // bias
    __shared__ int   sh_blk[CHUNK/BS];     // 2 block ids
    __shared__ float sh_red[3];            // M, L, merge flag

    if (t < CHUNK/BS) sh_blk[t] = btab[b*NTBL + PT_LEN + chunk*(CHUNK/BS) + t];
    if (t < CHUNK)    sh_b[t]   = bias[(size_t)bh*MAX_CTX + start + t];

    float4 q4 = ((const float4*)(q + (size_t)bh*DIM))[lane];
    q4.x *= QSCALE; q4.y *= QSCALE; q4.z *= QSCALE; q4.w *= QSCALE;
    const float vn = v_new[(size_t)bh*DIM + t];
    __syncthreads();

    // ---------- Phase A: warp `wid` streams rows wid*8..wid*8+7 via cp.async ----------
    {
        const int kb   = wid >> 1;                          // cache block (0/1)
        const int rb   = (wid & 1) * 8;                     // row offset inside block
        const float* kbase = kc + ((size_t)sh_blk[kb]*HEADS + h)*(BS*DIM) + rb*DIM;
        const float* knewp = k_new + (size_t)bh*DIM;
        const unsigned dbase = (unsigned)__cvta_generic_to_shared(&shK[wid*8*DIM]) + lane*16u;
        #pragma unroll
        for (int r = 0; r < 8; ++r) {
            const int pos = start + wid*8 + r;
            const float* src = ((pos == last) ? knewp : (kbase + r*DIM)) + lane*4;
            asm volatile("cp.async.cg.shared.global [%0], [%1], 16;\n"
                         :: "r"(dbase + r*(DIM*4u)), "l"(src) : "memory");
        }
        asm volatile("cp.async.commit_group;\n" ::: "memory");
        asm volatile("cp.async.wait_group 0;\n"  ::: "memory");
        __syncwarp();

        float sp[8];
        #pragma unroll
        for (int i = 0; i < 8; ++i) {
            const float4 k4 = *(const float4*)&shK[(wid*8 + i)*DIM + lane*4];
            sp[i] = q4.x*k4.x + q4.y*k4.y + q4.z*k4.z + q4.w*k4.w;
        }
        #pragma unroll
        for (int o = 16; o > 0; o >>= 1)
            #pragma unroll
            for (int i = 0; i < 8; ++i)
                sp[i] += __shfl_xor_sync(0xffffffffu, sp[i], o);
        if (lane == 0) {
            #pragma unroll
            for (int i = 0; i < 8; ++i) sh_s[wid*8 + i] = sp[i];
        }
    }
    __syncthreads();

    // ---------- Phase B: single-warp softmax over 32 scores ----------
    if (wid == 0) {
        const float sc = (lane < npos) ? sh_s[lane] + sh_b[lane] : NEG_INF;
        float mx = sc;
        #pragma unroll
        for (int o = 16; o > 0; o >>= 1) mx = fmaxf(mx, __shfl_xor_sync(0xffffffffu, mx, o));
        const float pv = __expf(sc - mx);              // masked -> exp(NEG_INF-M) = 0
        float sum = pv;
        #pragma unroll
        for (int o = 16; o > 0; o >>= 1) sum += __shfl_xor_sync(0xffffffffu, sum, o);
        sh_s[lane] = pv;
        if (lane == 0) { sh_red[0] = mx; sh_red[1] = sum; }
    }
    __syncthreads();
    const float M = sh_red[0];
    const float L = sh_red[1];

    // ---------- Phase C: V accumulate (thread t owns dim t; 2 blocks) ----------
    float acc = 0.f;
    #pragma unroll
    for (int kb = 0; kb < 2; ++kb) {
        const float4* vp = (const float4*)(vc + ((size_t)sh_blk[kb]*HEADS + h)*(DIM*BS) + t*BS);
        float4 v0 = vp[0], v1 = vp[1], v2 = vp[2], v3 = vp[3];
        float vv[16] = {v0.x,v0.y,v0.z,v0.w, v1.x,v1.y,v1.z,v1.w,
                        v2.x,v2.y,v2.z,v2.w, v3.x,v3.y,v3.z,v3.w};
        const int li = last - (start + kb*BS);
        #pragma unroll
        for (int j = 0; j < BS; ++j) {
            if (j == li) vv[j] = vn;                  // constant-index compare -> SEL
            acc += sh_s[kb*BS + j] * vv[j];
        }
    }

    const int nch = (ctx + CHUNK - 1) / CHUNK;
    if (nch == 1) {
        out[(size_t)bh*DIM + t] = acc / L;
        return;
    }

    // ---------- partial write + fan-in merge (last CTA for this (b,h)) ----------
    const int base = bh*NCHUNK;
    const int idx  = base + chunk;
    if (t == 0) { g_m[idx] = M; g_l[idx] = L; }
    g_acc[(size_t)idx*DIM + t] = acc;
    __threadfence();
    __syncthreads();
    if (t == 0) {
        const unsigned int ticket = atomicAdd(&g_cnt[bh], 1u);
        sh_red[2] = (ticket == (unsigned)(nch - 1)) ? 1.f : 0.f;
    }
    __syncthreads();
    if (sh_red[2] != 0.f) {
        float MM = NEG_INF;
        #pragma unroll 4
        for (int c = 0; c < nch; ++c) MM = fmaxf(MM, g_m[base + c]);
        float LL = 0.f, o = 0.f;
        #pragma unroll 4
        for (int c = 0; c < nch; ++c) {
            const float w = __expf(g_m[base + c] - MM);
            LL += g_l[base + c] * w;
            o  += w * g_acc[(size_t)(base + c)*DIM + t];
        }
        out[(size_t)bh*DIM + t] = o / LL;
        if (t == 0) g_cnt[bh] = 0u;
    }
}

extern "C" void kernel_launch(void* const* d_in, const int* in_sizes, int n_in,
                              void* d_out, int out_size)
{
    const float* q     = (const float*)d_in[0];
    const float* k_new = (const float*)d_in[1];
    const float* v_new = (const float*)d_in[2];
    const float* kc    = (const float*)d_in[3];
    const float* vc    = (const float*)d_in[4];
    const int*   btab  = (const int*)d_in[6];
    const int*   ctx   = (const int*)d_in[7];
    const float* bias  = (const float*)d_in[8];

    dim3 g(NCHUNK, HEADS, BATCH);
    attn_fused<<<g, 128>>>(q, k_new, v_new, kc, vc, btab, ctx, bias, (float*)d_out);
}